// round 16
// baseline (speedup 1.0000x reference)
#include <cuda_runtime.h>
#include <cuda_bf16.h>
#include <math.h>
#include <stdint.h>

// Problem dims
#define TT   512
#define BB   64
#define II   1024
#define HH   1024
#define N4H  4096
#define MTOT (TT*BB)        // 32768

// Step tiling
#define NCTA    128
#define NPC     32          // gate-output columns (p) per CTA
#define KCHUNK  64
#define NCHUNK  (HH/KCHUNK) // 16

// ---------------------------------------------------------------------------
// Device scratch (allocation-free)
// ---------------------------------------------------------------------------
__device__ float g_xp[(size_t)MTOT * N4H];         // input projections + bias, p-ordered
__device__ float g_c[BB * HH];                     // cell state (batch-major)
__device__ __nv_bfloat16 g_whi[(size_t)N4H * HH];  // Wh hi (p-ordered rows)
__device__ __nv_bfloat16 g_wlo[(size_t)N4H * HH];  // Wh lo
__device__ __nv_bfloat16 g_hhi[2][HH * BB];        // h hi, K-MAJOR [hidden][batch], ping-pong
__device__ __nv_bfloat16 g_hlo[2][HH * BB];        // h lo, K-MAJOR
__device__ __nv_bfloat16 g_xhi[(size_t)MTOT * II]; // X hi
__device__ __nv_bfloat16 g_xlo[(size_t)MTOT * II]; // X lo
__device__ __nv_bfloat16 g_wihi[(size_t)N4H * II]; // Wi hi (p-ordered rows)
__device__ __nv_bfloat16 g_wilo[(size_t)N4H * II]; // Wi lo
__device__ float g_bp[N4H];                        // bias, p-ordered
__device__ unsigned g_bar;                         // grid barrier counter

// ---------------------------------------------------------------------------
// Helpers
// ---------------------------------------------------------------------------
__device__ __forceinline__ uint32_t smem_u32(const void* p) {
    uint32_t a;
    asm("{ .reg .u64 t; cvta.to.shared.u64 t, %1; cvt.u32.u64 %0, t; }" : "=r"(a) : "l"(p));
    return a;
}
__device__ __forceinline__ void cp_async16(uint32_t smem_addr, const void* gptr) {
    asm volatile("cp.async.cg.shared.global [%0], [%1], 16;" :: "r"(smem_addr), "l"(gptr));
}
#define CP_COMMIT() asm volatile("cp.async.commit_group;" ::: "memory")

__device__ __forceinline__ void ldsm4(uint32_t* r, uint32_t addr) {
    asm volatile("ldmatrix.sync.aligned.m8n8.x4.shared.b16 {%0,%1,%2,%3}, [%4];"
                 : "=r"(r[0]), "=r"(r[1]), "=r"(r[2]), "=r"(r[3]) : "r"(addr));
}
__device__ __forceinline__ void ldsm4t(uint32_t* r, uint32_t addr) {
    asm volatile("ldmatrix.sync.aligned.m8n8.x4.trans.shared.b16 {%0,%1,%2,%3}, [%4];"
                 : "=r"(r[0]), "=r"(r[1]), "=r"(r[2]), "=r"(r[3]) : "r"(addr));
}
__device__ __forceinline__ void mma_bf16(float* d, const uint32_t* a, uint32_t b0, uint32_t b1) {
    asm volatile("mma.sync.aligned.m16n8k16.row.col.f32.bf16.bf16.f32 "
                 "{%0,%1,%2,%3}, {%4,%5,%6,%7}, {%8,%9}, {%0,%1,%2,%3};"
                 : "+f"(d[0]), "+f"(d[1]), "+f"(d[2]), "+f"(d[3])
                 : "r"(a[0]), "r"(a[1]), "r"(a[2]), "r"(a[3]), "r"(b0), "r"(b1));
}
// Fast activations: MUFU-based, error ~2^-21
__device__ __forceinline__ float sigmoidf_(float x) {
    return __fdividef(1.f, 1.f + __expf(-x));
}
__device__ __forceinline__ float tanhf_(float x) {
    return 2.f * __fdividef(1.f, 1.f + __expf(-2.f * x)) - 1.f;
}
#define SWZ(row, c16) ((uint32_t)((row) * 128 + (((c16) ^ ((row) & 7)) << 4)))

__device__ __forceinline__ uint32_t pk2(float a, float b) {
    __nv_bfloat16 x = __float2bfloat16(a), y = __float2bfloat16(b);
    uint16_t xa = *(uint16_t*)&x, yb = *(uint16_t*)&y;
    return (uint32_t)xa | ((uint32_t)yb << 16);
}

// ---------------------------------------------------------------------------
// Prep kernels (vectorized). prep_w handles Wh (p<4096) and Wi (p>=4096).
// ---------------------------------------------------------------------------
__global__ void prep_w(const float* __restrict__ wh0, const float* __restrict__ wh1,
                       const float* __restrict__ wh2, const float* __restrict__ wh3,
                       const float* __restrict__ wi0, const float* __restrict__ wi1,
                       const float* __restrict__ wi2, const float* __restrict__ wi3)
{
    const int pp = blockIdx.x;                // 0..8191
    const bool is_wi = pp >= N4H;
    const int p = is_wi ? pp - N4H : pp;
    const int j = p >> 2, g = p & 3;
    const float* w;
    if (is_wi) w = (g == 0) ? wi0 : (g == 1) ? wi1 : (g == 2) ? wi2 : wi3;
    else       w = (g == 0) ? wh0 : (g == 1) ? wh1 : (g == 2) ? wh2 : wh3;
    const float4 v0 = *(const float4*)&w[(size_t)j * HH + threadIdx.x * 8];
    const float4 v1 = *(const float4*)&w[(size_t)j * HH + threadIdx.x * 8 + 4];
    const float f[8] = {v0.x, v0.y, v0.z, v0.w, v1.x, v1.y, v1.z, v1.w};
    float lo[8];
#pragma unroll
    for (int i = 0; i < 8; i++)
        lo[i] = f[i] - __bfloat162float(__float2bfloat16(f[i]));
    size_t base = (size_t)p * HH + threadIdx.x * 8;
    uint4 vhi = make_uint4(pk2(f[0], f[1]), pk2(f[2], f[3]), pk2(f[4], f[5]), pk2(f[6], f[7]));
    uint4 vlo = make_uint4(pk2(lo[0], lo[1]), pk2(lo[2], lo[3]), pk2(lo[4], lo[5]), pk2(lo[6], lo[7]));
    if (is_wi) { *(uint4*)&g_wihi[base] = vhi; *(uint4*)&g_wilo[base] = vlo; }
    else       { *(uint4*)&g_whi[base]  = vhi; *(uint4*)&g_wlo[base]  = vlo; }
}

__global__ void prep_x(const float* __restrict__ X)
{
    size_t i = (size_t)blockIdx.x * blockDim.x + threadIdx.x;   // each: 8 floats
    const float4 v0 = ((const float4*)X)[i * 2];
    const float4 v1 = ((const float4*)X)[i * 2 + 1];
    const float f[8] = {v0.x, v0.y, v0.z, v0.w, v1.x, v1.y, v1.z, v1.w};
    float lo[8];
#pragma unroll
    for (int k = 0; k < 8; k++)
        lo[k] = f[k] - __bfloat162float(__float2bfloat16(f[k]));
    ((uint4*)g_xhi)[i] = make_uint4(pk2(f[0], f[1]), pk2(f[2], f[3]), pk2(f[4], f[5]), pk2(f[6], f[7]));
    ((uint4*)g_xlo)[i] = make_uint4(pk2(lo[0], lo[1]), pk2(lo[2], lo[3]), pk2(lo[4], lo[5]), pk2(lo[6], lo[7]));
}

// prep_h: h0 split into K-MAJOR hT; bias (first 4096 threads); barrier reset
__global__ void prep_h(const float* __restrict__ hx,
                       const float* __restrict__ b0, const float* __restrict__ b1,
                       const float* __restrict__ b2, const float* __restrict__ b3)
{
    int i = blockIdx.x * blockDim.x + threadIdx.x;   // 0..65535
    int b = i >> 10, j = i & 1023;                   // hx is [B][H]
    float v = hx[i];
    __nv_bfloat16 hi = __float2bfloat16(v);
    g_hhi[0][j * BB + b] = hi;
    g_hlo[0][j * BB + b] = __float2bfloat16(v - __bfloat162float(hi));
    if (i < N4H) {
        int jj = i >> 2, g = i & 3;
        const float* bb = (g == 0) ? b0 : (g == 1) ? b1 : (g == 2) ? b2 : b3;
        g_bp[i] = bb[jj];
    }
    if (i == 0) g_bar = 0u;
}

// ---------------------------------------------------------------------------
// Input projection on tensor cores (3-term split bf16) — unchanged (ceiling)
// ---------------------------------------------------------------------------
#define PA_HI 0
#define PA_LO 16384
#define PB_HI 32768
#define PB_LO 49152
#define PSTAGE 65536
#define PSMEM (3 * PSTAGE)   // 196608

__global__ __launch_bounds__(512) void proj_hmma_kernel()
{
    extern __shared__ char smem[];
    const uint32_t sbase = smem_u32(smem);
    const int tid = threadIdx.x;
    const int m0 = blockIdx.y * 128;
    const int n0 = blockIdx.x * 128;

    auto load_chunk = [&](int kc, int st) {
        const uint32_t sb = sbase + st * PSTAGE;
#pragma unroll
        for (int i = 0; i < 2; i++) {
            int u = tid + i * 512;
            int row = u >> 3, c16 = u & 7;
            uint32_t soff = SWZ(row, c16);
            size_t gx = ((size_t)(m0 + row) * II + kc * KCHUNK + c16 * 8) * 2;
            size_t gw = ((size_t)(n0 + row) * II + kc * KCHUNK + c16 * 8) * 2;
            cp_async16(sb + PA_HI + soff, (const char*)g_xhi + gx);
            cp_async16(sb + PA_LO + soff, (const char*)g_xlo + gx);
            cp_async16(sb + PB_HI + soff, (const char*)g_wihi + gw);
            cp_async16(sb + PB_LO + soff, (const char*)g_wilo + gw);
        }
        CP_COMMIT();
    };

    const int wid  = tid >> 5;
    const int lane = tid & 31;
    const int mrow = (wid & 3) * 32;
    const int ncol = (wid >> 2) * 32;
    const int grp  = lane >> 2;
    const int tig  = lane & 3;
    const int tile = lane >> 3;
    const int lr   = lane & 7;

    int a_r[2], b_r[2];
    a_r[0] = mrow + (tile & 1) * 8 + lr;
    a_r[1] = a_r[0] + 16;
    b_r[0] = ncol + (tile >> 1) * 8 + lr;
    b_r[1] = b_r[0] + 16;
    const int a_kt = tile >> 1;
    const int b_kt = tile & 1;

    float acc[2][4][4];
#pragma unroll
    for (int mt = 0; mt < 2; mt++)
#pragma unroll
        for (int n = 0; n < 4; n++)
#pragma unroll
            for (int i = 0; i < 4; i++) acc[mt][n][i] = 0.f;

    load_chunk(0, 0);
    load_chunk(1, 1);

    for (int kc = 0; kc < NCHUNK; kc++) {
        if (kc < NCHUNK - 1) asm volatile("cp.async.wait_group 1;" ::: "memory");
        else                 asm volatile("cp.async.wait_group 0;" ::: "memory");
        __syncthreads();

        if (kc + 2 < NCHUNK) load_chunk(kc + 2, (kc + 2) % 3);

        const uint32_t sb = sbase + (kc % 3) * PSTAGE;
#pragma unroll
        for (int ks = 0; ks < 4; ks++) {
            uint32_t ah[2][4], al[2][4], bh[2][4], bl[2][4];
#pragma unroll
            for (int mt = 0; mt < 2; mt++) {
                uint32_t ao = a_r[mt] * 128 + ((uint32_t)((ks * 2 + a_kt) ^ (a_r[mt] & 7)) << 4);
                ldsm4(ah[mt], sb + PA_HI + ao);
                ldsm4(al[mt], sb + PA_LO + ao);
            }
#pragma unroll
            for (int nt = 0; nt < 2; nt++) {
                uint32_t bo = b_r[nt] * 128 + ((uint32_t)((ks * 2 + b_kt) ^ (b_r[nt] & 7)) << 4);
                ldsm4(bh[nt], sb + PB_HI + bo);
                ldsm4(bl[nt], sb + PB_LO + bo);
            }
#pragma unroll
            for (int mt = 0; mt < 2; mt++)
#pragma unroll
                for (int nt = 0; nt < 2; nt++) {
                    mma_bf16(acc[mt][2 * nt],     ah[mt], bh[nt][0], bh[nt][1]);
                    mma_bf16(acc[mt][2 * nt + 1], ah[mt], bh[nt][2], bh[nt][3]);
                    mma_bf16(acc[mt][2 * nt],     ah[mt], bl[nt][0], bl[nt][1]);
                    mma_bf16(acc[mt][2 * nt + 1], ah[mt], bl[nt][2], bl[nt][3]);
                    mma_bf16(acc[mt][2 * nt],     al[mt], bh[nt][0], bh[nt][1]);
                    mma_bf16(acc[mt][2 * nt + 1], al[mt], bh[nt][2], bh[nt][3]);
                }
        }
    }

#pragma unroll
    for (int mt = 0; mt < 2; mt++) {
        const int r0 = m0 + mrow + mt * 16 + grp;
#pragma unroll
        for (int n8 = 0; n8 < 4; n8++) {
            const int col = n0 + ncol + n8 * 8 + 2 * tig;
            const float b0 = g_bp[col], b1 = g_bp[col + 1];
            float2 v0 = make_float2(acc[mt][n8][0] + b0, acc[mt][n8][1] + b1);
            float2 v1 = make_float2(acc[mt][n8][2] + b0, acc[mt][n8][3] + b1);
            *(float2*)&g_xp[(size_t)r0 * N4H + col]       = v0;
            *(float2*)&g_xp[(size_t)(r0 + 8) * N4H + col] = v1;
        }
    }
}

// ---------------------------------------------------------------------------
// Persistent recurrent kernel: K-major h + warp-private A pipeline.
// Each warp (ks,mpos) cp.asyncs its own 16 k-rows x 64B half-rows per chunk
// (coalesced) and gates ONLY on its own wait_group -> no block syncs in the
// mainloop. A fragments via ldmatrix.trans. 5-stage ring, depth-4 prefetch.
// Syncs/step: 1 pre-ep + 1 ep + 2 barrier (was 18).
// ---------------------------------------------------------------------------
#define W_HI_OFF 0
#define W_LO_OFF 65536
#define A_BASE   131072
#define A_ST(s)  (A_BASE + (s) * 16384)     // 5 stages x 16KB (hi 8K + lo 8K)
#define EP_OFF   A_BASE                     // epilogue scratch overlays A stages
#define XP_OFF   212992                     // 2 x 8KB xp double buffer
#define SMEM_TOTAL 229376                   // 224KB

__global__ __launch_bounds__(256) void lstm_persist_kernel(
    const float* __restrict__ cx_in, float* __restrict__ out)
{
    extern __shared__ char smem[];
    const uint32_t sbase = smem_u32(smem);
    const int tid = threadIdx.x;
    const int cta = blockIdx.x;

    // one-time: weights (hi+lo) into SMEM, chunk-major, swizzled
    {
#pragma unroll
        for (int i = 0; i < 16; i++) {
            int u = tid + i * 256;            // 0..4095
            int kc  = u >> 8;
            int row = (u & 255) >> 3;
            int c16 = u & 7;
            uint32_t soff = (uint32_t)(kc * 4096) + SWZ(row, c16);
            size_t   goff = (size_t)(cta * NPC + row) * (HH * 2) + (size_t)kc * 128 + c16 * 16;
            cp_async16(sbase + W_HI_OFF + soff, (const char*)g_whi + goff);
            cp_async16(sbase + W_LO_OFF + soff, (const char*)g_wlo + goff);
        }
        CP_COMMIT();
        asm volatile("cp.async.wait_group 0;" ::: "memory");
        __syncthreads();
    }

    // warp/lane mapping: (mpos, ks), warp tile m32 x n32
    const int wid  = tid >> 5;
    const int lane = tid & 31;
    const int ks   = wid & 3;
    const int mpos = wid >> 2;
    const int grp  = lane >> 2;
    const int tig  = lane & 3;
    const int tile = lane >> 3;
    const int lr   = lane & 7;

    // warp-private A loads: 2 hi + 2 lo cp.async per lane per chunk.
    // hT is K-major: row k = 128B of 64 batches; warp takes rows ks*16..+16,
    // batch half mpos (64B).
    uint32_t a_soff[2];
    size_t   a_goff[2];
#pragma unroll
    for (int i = 0; i < 2; i++) {
        int krow = ks * 16 + i * 8 + (lane >> 2);    // row within chunk
        int seg  = lane & 3;                          // 16B segment within 64B half
        int col16 = mpos * 4 + seg;
        a_soff[i] = (uint32_t)(krow * 128 + ((col16 ^ (krow & 7)) << 4));
        a_goff[i] = (size_t)krow * 128 + mpos * 64 + seg * 16;  // + c*8192 at load
    }

    // xp staging mapping (block-wide, unchanged)
    uint32_t xp_soff[2];
    size_t   xp_goff[2];
#pragma unroll
    for (int i = 0; i < 2; i++) {
        int u = tid + i * 256;
        int row = u >> 3, c16 = u & 7;
        xp_soff[i] = (uint32_t)(u * 16);
        xp_goff[i] = ((size_t)row * N4H + cta * NPC + c16 * 4) * 4;
    }

    // ldsm.trans A offsets: fragment f covers m (mpos*32 + f*16 .. +16)
    const int krow_t = ks * 16 + (tile >> 1) * 8 + lr;   // k-row within chunk
    const int colA0  = mpos * 4 + (tile & 1);            // fragment 0 16B col
    const int colA1  = colA0 + 2;                        // fragment 1
    const uint32_t a_off0 = (uint32_t)(krow_t * 128 + ((colA0 ^ (krow_t & 7)) << 4));
    const uint32_t a_off1 = (uint32_t)(krow_t * 128 + ((colA1 ^ (krow_t & 7)) << 4));

    // B offsets (weights, unchanged)
    const int b_row = (tile >> 1) * 8 + lr;
    const int b_kt  = tile & 1;
    const uint32_t b_off0 = (uint32_t)(b_row * 128) +
                            ((uint32_t)((ks * 2 + b_kt) ^ (b_row & 7)) << 4);
    const uint32_t b_off1 = b_off0 + 16 * 128;

    float* ep = (float*)(smem + EP_OFF);
    float* myep = ep + ks * 2304;

    auto xp_prefetch = [&](int tn) {
        const char* xg = (const char*)(g_xp + (size_t)tn * BB * N4H);
        const uint32_t xb = sbase + XP_OFF + (uint32_t)((tn & 1) * 8192);
#pragma unroll
        for (int i = 0; i < 2; i++)
            cp_async16(xb + xp_soff[i], xg + xp_goff[i]);
        CP_COMMIT();
    };

    xp_prefetch(0);

    for (int t = 0; t < TT; t++) {
        const float* __restrict__ cprev = (t == 0) ? cx_in : g_c;
        const __nv_bfloat16* __restrict__ hhi = g_hhi[t & 1];
        const __nv_bfloat16* __restrict__ hlo = g_hlo[t & 1];
        __nv_bfloat16* __restrict__ nhhi = g_hhi[(t + 1) & 1];
        __nv_bfloat16* __restrict__ nhlo = g_hlo[(t + 1) & 1];
        float* __restrict__ out_t = out + (size_t)t * (BB * HH);
        const float* xp_s = (const float*)(smem + XP_OFF + (t & 1) * 8192);

        auto load_chunk = [&](int kc, int st) {
            const uint32_t sb = sbase + A_ST(st);
            const size_t kb = (size_t)kc * 8192;      // 64 rows x 128B
#pragma unroll
            for (int i = 0; i < 2; i++) {
                cp_async16(sb + a_soff[i],        (const char*)hhi + a_goff[i] + kb);
                cp_async16(sb + 8192 + a_soff[i], (const char*)hlo + a_goff[i] + kb);
            }
            CP_COMMIT();
        };

        load_chunk(0, 0);
        load_chunk(1, 1);
        load_chunk(2, 2);
        load_chunk(3, 3);

        float acc_h[2][4][4];
        float acc_m[2][4][4];
#pragma unroll
        for (int mt = 0; mt < 2; mt++)
#pragma unroll
            for (int nt = 0; nt < 4; nt++)
#pragma unroll
                for (int i = 0; i < 4; i++) { acc_h[mt][nt][i] = 0.f; acc_m[mt][nt][i] = 0.f; }

        // NO block syncs: each warp gates on its own cp.async groups.
        for (int c = 0; c < NCHUNK; c++) {
            if (c <= NCHUNK - 4)      asm volatile("cp.async.wait_group 3;" ::: "memory");
            else if (c == NCHUNK - 3) asm volatile("cp.async.wait_group 2;" ::: "memory");
            else if (c == NCHUNK - 2) asm volatile("cp.async.wait_group 1;" ::: "memory");
            else                      asm volatile("cp.async.wait_group 0;" ::: "memory");

            if (c + 4 < NCHUNK) load_chunk(c + 4, (c + 4) % 5);

            const uint32_t asb = sbase + A_ST(c % 5);
            const uint32_t whb = sbase + W_HI_OFF + (uint32_t)(c * 4096);

            uint32_t ah0[4], ah1[4], al0[4], al1[4], bh0[4], bh1[4], bl0[4], bl1[4];
            ldsm4t(ah0, asb + a_off0);
            ldsm4t(ah1, asb + a_off1);
            ldsm4(bh0, whb + b_off0);
            ldsm4(bh1, whb + b_off1);
            ldsm4t(al0, asb + 8192 + a_off0);
            ldsm4t(al1, asb + 8192 + a_off1);
            ldsm4(bl0, whb + 65536 + b_off0);
            ldsm4(bl1, whb + 65536 + b_off1);

            // hi*hi
            mma_bf16(acc_h[0][0], ah0, bh0[0], bh0[1]);
            mma_bf16(acc_h[0][1], ah0, bh0[2], bh0[3]);
            mma_bf16(acc_h[0][2], ah0, bh1[0], bh1[1]);
            mma_bf16(acc_h[0][3], ah0, bh1[2], bh1[3]);
            mma_bf16(acc_h[1][0], ah1, bh0[0], bh0[1]);
            mma_bf16(acc_h[1][1], ah1, bh0[2], bh0[3]);
            mma_bf16(acc_h[1][2], ah1, bh1[0], bh1[1]);
            mma_bf16(acc_h[1][3], ah1, bh1[2], bh1[3]);
            // hi*lo
            mma_bf16(acc_m[0][0], ah0, bl0[0], bl0[1]);
            mma_bf16(acc_m[0][1], ah0, bl0[2], bl0[3]);
            mma_bf16(acc_m[0][2], ah0, bl1[0], bl1[1]);
            mma_bf16(acc_m[0][3], ah0, bl1[2], bl1[3]);
            mma_bf16(acc_m[1][0], ah1, bl0[0], bl0[1]);
            mma_bf16(acc_m[1][1], ah1, bl0[2], bl0[3]);
            mma_bf16(acc_m[1][2], ah1, bl1[0], bl1[1]);
            mma_bf16(acc_m[1][3], ah1, bl1[2], bl1[3]);
            // lo*hi
            mma_bf16(acc_m[0][0], al0, bh0[0], bh0[1]);
            mma_bf16(acc_m[0][1], al0, bh0[2], bh0[3]);
            mma_bf16(acc_m[0][2], al0, bh1[0], bh1[1]);
            mma_bf16(acc_m[0][3], al0, bh1[2], bh1[3]);
            mma_bf16(acc_m[1][0], al1, bh0[0], bh0[1]);
            mma_bf16(acc_m[1][1], al1, bh0[2], bh0[3]);
            mma_bf16(acc_m[1][2], al1, bh1[0], bh1[1]);
            mma_bf16(acc_m[1][3], al1, bh1[2], bh1[3]);
        }

        // ---- k-partial reduction + fused LSTM epilogue ----
        __syncthreads();                   // all warps done before ep overlays A
#pragma unroll
        for (int mt = 0; mt < 2; mt++) {
            const int r = mpos * 32 + mt * 16 + grp;
#pragma unroll
            for (int n8 = 0; n8 < 4; n8++) {
                const int ci = n8 * 8 + 2 * tig;
                myep[r * 36 + ci]           = acc_h[mt][n8][0] + acc_m[mt][n8][0];
                myep[r * 36 + ci + 1]       = acc_h[mt][n8][1] + acc_m[mt][n8][1];
                myep[(r + 8) * 36 + ci]     = acc_h[mt][n8][2] + acc_m[mt][n8][2];
                myep[(r + 8) * 36 + ci + 1] = acc_h[mt][n8][3] + acc_m[mt][n8][3];
            }
        }
        __syncthreads();

        // xp(t+1) prefetch now (separate buffer; hides under epilogue+barrier)
        if (t + 1 < TT) xp_prefetch(t + 1);

        {
            const int b   = tid >> 2;
            const int jj0 = (tid & 3) * 2;
            const int j0  = cta * 8 + jj0;
            const float2 cpv = *(const float2*)&cprev[b * HH + j0];
            float hq[2], cq[2];
#pragma unroll
            for (int q = 0; q < 2; q++) {
                const int jj = jj0 + q;
                float4 r0 = *(const float4*)&ep[b * 36 + jj * 4];
                float4 r1 = *(const float4*)&ep[2304 + b * 36 + jj * 4];
                float4 r2 = *(const float4*)&ep[4608 + b * 36 + jj * 4];
                float4 r3 = *(const float4*)&ep[6912 + b * 36 + jj * 4];
                float4 xv = *(const float4*)&xp_s[b * 32 + jj * 4];
                float gi = (r0.x + r1.x) + (r2.x + r3.x) + xv.x;
                float gf = (r0.y + r1.y) + (r2.y + r3.y) + xv.y;
                float ga = (r0.z + r1.z) + (r2.z + r3.z) + xv.z;
                float go = (r0.w + r1.w) + (r2.w + r3.w) + xv.w;
                float ig = sigmoidf_(gi);
                float fg = sigmoidf_(gf);
                float ag = tanhf_(ga);
                float og = sigmoidf_(go);
                float cp = (q == 0) ? cpv.x : cpv.y;
                cq[q] = fg * cp + ig * ag;
                hq[q] = og * tanhf_(cq[q]);
            }
            *(float2*)&g_c[b * HH + j0]   = make_float2(cq[0], cq[1]);
            *(float2*)&out_t[b * HH + j0] = make_float2(hq[0], hq[1]);
            // h split stores into K-MAJOR hT (2B scatters, 16B runs per warp-row)
            __nv_bfloat16 h0 = __float2bfloat16(hq[0]);
            __nv_bfloat16 h1 = __float2bfloat16(hq[1]);
            nhhi[(size_t)j0 * BB + b]       = h0;
            nhhi[(size_t)(j0 + 1) * BB + b] = h1;
            nhlo[(size_t)j0 * BB + b]       = __float2bfloat16(hq[0] - __bfloat162float(h0));
            nhlo[(size_t)(j0 + 1) * BB + b] = __float2bfloat16(hq[1] - __bfloat162float(h1));
            if (t == TT - 1) {             // fused finalize: hy, cy
                const size_t TBH = (size_t)TT * BB * HH;
                *(float2*)&out[TBH + b * HH + j0]                   = make_float2(hq[0], hq[1]);
                *(float2*)&out[TBH + (size_t)BB * HH + b * HH + j0] = make_float2(cq[0], cq[1]);
            }
        }

        // ---- global barrier (tid0-only pure-spin poll, release-atomic arrive) ----
        if (t + 1 < TT) {
            __syncthreads();
            if (tid == 0) {
                asm volatile("red.release.gpu.global.add.u32 [%0], 1;"
                             :: "l"(&g_bar) : "memory");
                const unsigned target = (unsigned)NCTA * (unsigned)(t + 1);
                unsigned v;
                do {
                    asm volatile("ld.global.acquire.gpu.u32 %0, [%1];"
                                 : "=r"(v) : "l"(&g_bar));
                } while (v < target);
            }
            __syncthreads();
        }
    }
}

// ---------------------------------------------------------------------------
extern "C" void kernel_launch(void* const* d_in, const int* in_sizes, int n_in,
                              void* d_out, int out_size)
{
    const float* X    = (const float*)d_in[0];
    const float* hx   = (const float*)d_in[1];
    const float* cx   = (const float*)d_in[2];
    const float* w_ii = (const float*)d_in[3];
    const float* w_fi = (const float*)d_in[4];
    const float* w_ai = (const float*)d_in[5];
    const float* w_oi = (const float*)d_in[6];
    const float* w_ih = (const float*)d_in[7];
    const float* w_fh = (const float*)d_in[8];
    const float* w_ah = (const float*)d_in[9];
    const float* w_oh = (const float*)d_in[10];
    const float* b_i  = (const float*)d_in[11];
    const float* b_f  = (const float*)d_in[12];
    const float* b_a  = (const float*)d_in[13];
    const float* b_o  = (const float*)d_in[14];
    float* out = (float*)d_out;

    (void)in_sizes; (void)n_in; (void)out_size;

    cudaFuncSetAttribute(proj_hmma_kernel,
                         cudaFuncAttributeMaxDynamicSharedMemorySize, PSMEM);
    cudaFuncSetAttribute(lstm_persist_kernel,
                         cudaFuncAttributeMaxDynamicSharedMemorySize, SMEM_TOTAL);

    prep_w<<<2 * N4H, 128>>>(w_ih, w_fh, w_ah, w_oh, w_ii, w_fi, w_ai, w_oi);
    prep_x<<<(int)((size_t)MTOT * II / 8 / 256), 256>>>(X);
    prep_h<<<(BB * HH) / 256, 256>>>(hx, b_i, b_f, b_a, b_o);

    dim3 pg(N4H / 128, MTOT / 128);
    proj_hmma_kernel<<<pg, 512, PSMEM>>>();

    lstm_persist_kernel<<<NCTA, 256, SMEM_TOTAL>>>(cx, out);
}

// round 17
// speedup vs baseline: 1.0069x; 1.0069x over previous
#include <cuda_runtime.h>
#include <cuda_bf16.h>
#include <math.h>
#include <stdint.h>

// Problem dims
#define TT   512
#define BB   64
#define II   1024
#define HH   1024
#define N4H  4096
#define MTOT (TT*BB)        // 32768

// Step tiling
#define NCTA    128
#define NPC     32          // gate-output columns (p) per CTA
#define KCHUNK  64
#define NCHUNK  (HH/KCHUNK) // 16

// ---------------------------------------------------------------------------
// Device scratch (allocation-free)
// ---------------------------------------------------------------------------
__device__ float g_xp[(size_t)MTOT * N4H];         // input projections + bias, p-ordered
__device__ float g_c[BB * HH];                     // cell state
__device__ __nv_bfloat16 g_whi[(size_t)N4H * HH];  // Wh hi (p-ordered rows)
__device__ __nv_bfloat16 g_wlo[(size_t)N4H * HH];  // Wh lo
__device__ __nv_bfloat16 g_hhi[2][BB * HH];        // h hi ping-pong (batch-major)
__device__ __nv_bfloat16 g_hlo[2][BB * HH];        // h lo
__device__ __nv_bfloat16 g_xhi[(size_t)MTOT * II]; // X hi
__device__ __nv_bfloat16 g_xlo[(size_t)MTOT * II]; // X lo
__device__ __nv_bfloat16 g_wihi[(size_t)N4H * II]; // Wi hi (p-ordered rows)
__device__ __nv_bfloat16 g_wilo[(size_t)N4H * II]; // Wi lo
__device__ float g_bp[N4H];                        // bias, p-ordered
__device__ unsigned g_bar;                         // grid barrier counter

// ---------------------------------------------------------------------------
// Helpers
// ---------------------------------------------------------------------------
__device__ __forceinline__ uint32_t smem_u32(const void* p) {
    uint32_t a;
    asm("{ .reg .u64 t; cvta.to.shared.u64 t, %1; cvt.u32.u64 %0, t; }" : "=r"(a) : "l"(p));
    return a;
}
__device__ __forceinline__ void cp_async16(uint32_t smem_addr, const void* gptr) {
    asm volatile("cp.async.cg.shared.global [%0], [%1], 16;" :: "r"(smem_addr), "l"(gptr));
}
#define CP_COMMIT() asm volatile("cp.async.commit_group;" ::: "memory")

__device__ __forceinline__ void ldsm4(uint32_t* r, uint32_t addr) {
    asm volatile("ldmatrix.sync.aligned.m8n8.x4.shared.b16 {%0,%1,%2,%3}, [%4];"
                 : "=r"(r[0]), "=r"(r[1]), "=r"(r[2]), "=r"(r[3]) : "r"(addr));
}
__device__ __forceinline__ void mma_bf16(float* d, const uint32_t* a, uint32_t b0, uint32_t b1) {
    asm volatile("mma.sync.aligned.m16n8k16.row.col.f32.bf16.bf16.f32 "
                 "{%0,%1,%2,%3}, {%4,%5,%6,%7}, {%8,%9}, {%0,%1,%2,%3};"
                 : "+f"(d[0]), "+f"(d[1]), "+f"(d[2]), "+f"(d[3])
                 : "r"(a[0]), "r"(a[1]), "r"(a[2]), "r"(a[3]), "r"(b0), "r"(b1));
}
// Fast activations: MUFU-based, error ~2^-21 (keeps rel_err headroom)
__device__ __forceinline__ float sigmoidf_(float x) {
    return __fdividef(1.f, 1.f + __expf(-x));
}
__device__ __forceinline__ float tanhf_(float x) {
    return 2.f * __fdividef(1.f, 1.f + __expf(-2.f * x)) - 1.f;
}
#define SWZ(row, c16) ((uint32_t)((row) * 128 + (((c16) ^ ((row) & 7)) << 4)))

__device__ __forceinline__ uint32_t pk2(float a, float b) {
    __nv_bfloat16 x = __float2bfloat16(a), y = __float2bfloat16(b);
    uint16_t xa = *(uint16_t*)&x, yb = *(uint16_t*)&y;
    return (uint32_t)xa | ((uint32_t)yb << 16);
}

// ---------------------------------------------------------------------------
// Prep kernels (vectorized). prep_w handles Wh (p<4096) and Wi (p>=4096).
// ---------------------------------------------------------------------------
__global__ void prep_w(const float* __restrict__ wh0, const float* __restrict__ wh1,
                       const float* __restrict__ wh2, const float* __restrict__ wh3,
                       const float* __restrict__ wi0, const float* __restrict__ wi1,
                       const float* __restrict__ wi2, const float* __restrict__ wi3)
{
    const int pp = blockIdx.x;                // 0..8191
    const bool is_wi = pp >= N4H;
    const int p = is_wi ? pp - N4H : pp;
    const int j = p >> 2, g = p & 3;
    const float* w;
    if (is_wi) w = (g == 0) ? wi0 : (g == 1) ? wi1 : (g == 2) ? wi2 : wi3;
    else       w = (g == 0) ? wh0 : (g == 1) ? wh1 : (g == 2) ? wh2 : wh3;
    const float4 v0 = *(const float4*)&w[(size_t)j * HH + threadIdx.x * 8];
    const float4 v1 = *(const float4*)&w[(size_t)j * HH + threadIdx.x * 8 + 4];
    const float f[8] = {v0.x, v0.y, v0.z, v0.w, v1.x, v1.y, v1.z, v1.w};
    float lo[8];
#pragma unroll
    for (int i = 0; i < 8; i++)
        lo[i] = f[i] - __bfloat162float(__float2bfloat16(f[i]));
    size_t base = (size_t)p * HH + threadIdx.x * 8;
    uint4 vhi = make_uint4(pk2(f[0], f[1]), pk2(f[2], f[3]), pk2(f[4], f[5]), pk2(f[6], f[7]));
    uint4 vlo = make_uint4(pk2(lo[0], lo[1]), pk2(lo[2], lo[3]), pk2(lo[4], lo[5]), pk2(lo[6], lo[7]));
    if (is_wi) { *(uint4*)&g_wihi[base] = vhi; *(uint4*)&g_wilo[base] = vlo; }
    else       { *(uint4*)&g_whi[base]  = vhi; *(uint4*)&g_wlo[base]  = vlo; }
}

__global__ void prep_x(const float* __restrict__ X)
{
    size_t i = (size_t)blockIdx.x * blockDim.x + threadIdx.x;   // each: 8 floats
    const float4 v0 = ((const float4*)X)[i * 2];
    const float4 v1 = ((const float4*)X)[i * 2 + 1];
    const float f[8] = {v0.x, v0.y, v0.z, v0.w, v1.x, v1.y, v1.z, v1.w};
    float lo[8];
#pragma unroll
    for (int k = 0; k < 8; k++)
        lo[k] = f[k] - __bfloat162float(__float2bfloat16(f[k]));
    ((uint4*)g_xhi)[i] = make_uint4(pk2(f[0], f[1]), pk2(f[2], f[3]), pk2(f[4], f[5]), pk2(f[6], f[7]));
    ((uint4*)g_xlo)[i] = make_uint4(pk2(lo[0], lo[1]), pk2(lo[2], lo[3]), pk2(lo[4], lo[5]), pk2(lo[6], lo[7]));
}

// prep_h also handles bias (first 4096 threads) and barrier reset
__global__ void prep_h(const float* __restrict__ hx,
                       const float* __restrict__ b0, const float* __restrict__ b1,
                       const float* __restrict__ b2, const float* __restrict__ b3)
{
    int i = blockIdx.x * blockDim.x + threadIdx.x;
    float v = hx[i];
    __nv_bfloat16 hi = __float2bfloat16(v);
    g_hhi[0][i] = hi;
    g_hlo[0][i] = __float2bfloat16(v - __bfloat162float(hi));
    if (i < N4H) {
        int j = i >> 2, g = i & 3;
        const float* b = (g == 0) ? b0 : (g == 1) ? b1 : (g == 2) ? b2 : b3;
        g_bp[i] = b[j];
    }
    if (i == 0) g_bar = 0u;                  // reset barrier each replay
}

// ---------------------------------------------------------------------------
// Input projection on tensor cores (3-term split bf16) — at MMA ceiling
// ---------------------------------------------------------------------------
#define PA_HI 0
#define PA_LO 16384
#define PB_HI 32768
#define PB_LO 49152
#define PSTAGE 65536
#define PSMEM (3 * PSTAGE)   // 196608

__global__ __launch_bounds__(512) void proj_hmma_kernel()
{
    extern __shared__ char smem[];
    const uint32_t sbase = smem_u32(smem);
    const int tid = threadIdx.x;
    const int m0 = blockIdx.y * 128;
    const int n0 = blockIdx.x * 128;

    auto load_chunk = [&](int kc, int st) {
        const uint32_t sb = sbase + st * PSTAGE;
#pragma unroll
        for (int i = 0; i < 2; i++) {
            int u = tid + i * 512;
            int row = u >> 3, c16 = u & 7;
            uint32_t soff = SWZ(row, c16);
            size_t gx = ((size_t)(m0 + row) * II + kc * KCHUNK + c16 * 8) * 2;
            size_t gw = ((size_t)(n0 + row) * II + kc * KCHUNK + c16 * 8) * 2;
            cp_async16(sb + PA_HI + soff, (const char*)g_xhi + gx);
            cp_async16(sb + PA_LO + soff, (const char*)g_xlo + gx);
            cp_async16(sb + PB_HI + soff, (const char*)g_wihi + gw);
            cp_async16(sb + PB_LO + soff, (const char*)g_wilo + gw);
        }
        CP_COMMIT();
    };

    const int wid  = tid >> 5;
    const int lane = tid & 31;
    const int mrow = (wid & 3) * 32;
    const int ncol = (wid >> 2) * 32;
    const int grp  = lane >> 2;
    const int tig  = lane & 3;
    const int tile = lane >> 3;
    const int lr   = lane & 7;

    int a_r[2], b_r[2];
    a_r[0] = mrow + (tile & 1) * 8 + lr;
    a_r[1] = a_r[0] + 16;
    b_r[0] = ncol + (tile >> 1) * 8 + lr;
    b_r[1] = b_r[0] + 16;
    const int a_kt = tile >> 1;
    const int b_kt = tile & 1;

    float acc[2][4][4];
#pragma unroll
    for (int mt = 0; mt < 2; mt++)
#pragma unroll
        for (int n = 0; n < 4; n++)
#pragma unroll
            for (int i = 0; i < 4; i++) acc[mt][n][i] = 0.f;

    load_chunk(0, 0);
    load_chunk(1, 1);

    for (int kc = 0; kc < NCHUNK; kc++) {
        if (kc < NCHUNK - 1) asm volatile("cp.async.wait_group 1;" ::: "memory");
        else                 asm volatile("cp.async.wait_group 0;" ::: "memory");
        __syncthreads();

        if (kc + 2 < NCHUNK) load_chunk(kc + 2, (kc + 2) % 3);

        const uint32_t sb = sbase + (kc % 3) * PSTAGE;
#pragma unroll
        for (int ks = 0; ks < 4; ks++) {
            uint32_t ah[2][4], al[2][4], bh[2][4], bl[2][4];
#pragma unroll
            for (int mt = 0; mt < 2; mt++) {
                uint32_t ao = a_r[mt] * 128 + ((uint32_t)((ks * 2 + a_kt) ^ (a_r[mt] & 7)) << 4);
                ldsm4(ah[mt], sb + PA_HI + ao);
                ldsm4(al[mt], sb + PA_LO + ao);
            }
#pragma unroll
            for (int nt = 0; nt < 2; nt++) {
                uint32_t bo = b_r[nt] * 128 + ((uint32_t)((ks * 2 + b_kt) ^ (b_r[nt] & 7)) << 4);
                ldsm4(bh[nt], sb + PB_HI + bo);
                ldsm4(bl[nt], sb + PB_LO + bo);
            }
#pragma unroll
            for (int mt = 0; mt < 2; mt++)
#pragma unroll
                for (int nt = 0; nt < 2; nt++) {
                    mma_bf16(acc[mt][2 * nt],     ah[mt], bh[nt][0], bh[nt][1]);
                    mma_bf16(acc[mt][2 * nt + 1], ah[mt], bh[nt][2], bh[nt][3]);
                    mma_bf16(acc[mt][2 * nt],     ah[mt], bl[nt][0], bl[nt][1]);
                    mma_bf16(acc[mt][2 * nt + 1], ah[mt], bl[nt][2], bl[nt][3]);
                    mma_bf16(acc[mt][2 * nt],     al[mt], bh[nt][0], bh[nt][1]);
                    mma_bf16(acc[mt][2 * nt + 1], al[mt], bh[nt][2], bh[nt][3]);
                }
        }
    }

#pragma unroll
    for (int mt = 0; mt < 2; mt++) {
        const int r0 = m0 + mrow + mt * 16 + grp;
#pragma unroll
        for (int n8 = 0; n8 < 4; n8++) {
            const int col = n0 + ncol + n8 * 8 + 2 * tig;
            const float b0 = g_bp[col], b1 = g_bp[col + 1];
            float2 v0 = make_float2(acc[mt][n8][0] + b0, acc[mt][n8][1] + b1);
            float2 v1 = make_float2(acc[mt][n8][2] + b0, acc[mt][n8][3] + b1);
            *(float2*)&g_xp[(size_t)r0 * N4H + col]       = v0;
            *(float2*)&g_xp[(size_t)(r0 + 8) * N4H + col] = v1;
        }
    }
}

// ---------------------------------------------------------------------------
// Persistent recurrent kernel (R15 winner + deferred out_t stores: the fp32
// output/finalize STGs happen AFTER the barrier arrive, overlapped with the
// tid0 spin — only nh/g_c stores gate the barrier).
// 256 threads / 8 warps = (2 m-pos x 4 k-slices), warp tile m32 x n32.
// ---------------------------------------------------------------------------
#define W_HI_OFF 0
#define W_LO_OFF 65536
#define A_BASE   131072
#define A_ST(s)  (A_BASE + (s) * 16384)     // 5 stages x 16KB (hi 8K + lo 8K)
#define EP_OFF   A_BASE                     // epilogue scratch overlays A stages
#define XP_OFF   212992                     // 2 x 8KB xp double buffer
#define SMEM_TOTAL 229376                   // 224KB

__global__ __launch_bounds__(256) void lstm_persist_kernel(
    const float* __restrict__ cx_in, float* __restrict__ out)
{
    extern __shared__ char smem[];
    const uint32_t sbase = smem_u32(smem);
    const int tid = threadIdx.x;
    const int cta = blockIdx.x;

    // one-time: weights (hi+lo) into SMEM, chunk-major, swizzled
    {
#pragma unroll
        for (int i = 0; i < 16; i++) {
            int u = tid + i * 256;            // 0..4095
            int kc  = u >> 8;
            int row = (u & 255) >> 3;
            int c16 = u & 7;
            uint32_t soff = (uint32_t)(kc * 4096) + SWZ(row, c16);
            size_t   goff = (size_t)(cta * NPC + row) * (HH * 2) + (size_t)kc * 128 + c16 * 16;
            cp_async16(sbase + W_HI_OFF + soff, (const char*)g_whi + goff);
            cp_async16(sbase + W_LO_OFF + soff, (const char*)g_wlo + goff);
        }
        CP_COMMIT();
        asm volatile("cp.async.wait_group 0;" ::: "memory");
        __syncthreads();
    }

    // A-load mapping: 2 hi + 2 lo cp.async per thread per chunk
    uint32_t a_soff[2];
    size_t   a_goff[2];
    uint32_t xp_soff[2];
    size_t   xp_goff[2];
#pragma unroll
    for (int i = 0; i < 2; i++) {
        int u = tid + i * 256;               // 0..511
        int row = u >> 3, c16 = u & 7;
        a_soff[i] = SWZ(row, c16);
        a_goff[i] = (size_t)row * (HH * 2) + c16 * 16;
        xp_soff[i] = (uint32_t)(u * 16);
        xp_goff[i] = ((size_t)row * N4H + cta * NPC + c16 * 4) * 4;
    }

    // warp/lane mapping: (mpos, ks), warp tile m32 x n32
    const int wid  = tid >> 5;
    const int lane = tid & 31;
    const int ks   = wid & 3;
    const int mpos = wid >> 2;
    const int grp  = lane >> 2;
    const int tig  = lane & 3;
    const int tile = lane >> 3;
    const int lr   = lane & 7;

    const int a_row0 = mpos * 32 + (tile & 1) * 8 + lr;
    const int a_kt   = tile >> 1;
    const int b_row  = (tile >> 1) * 8 + lr;
    const int b_kt   = tile & 1;

    const uint32_t a_off0 = (uint32_t)(a_row0 * 128) +
                            ((uint32_t)((ks * 2 + a_kt) ^ (a_row0 & 7)) << 4);
    const uint32_t a_off1 = a_off0 + 16 * 128;
    const uint32_t b_off0 = (uint32_t)(b_row * 128) +
                            ((uint32_t)((ks * 2 + b_kt) ^ (b_row & 7)) << 4);
    const uint32_t b_off1 = b_off0 + 16 * 128;

    float* ep = (float*)(smem + EP_OFF);
    float* myep = ep + ks * 2304;

    // xp prefetch (own commit group; source g_xp is static after proj)
    auto xp_prefetch = [&](int tn) {
        const char* xg = (const char*)(g_xp + (size_t)tn * BB * N4H);
        const uint32_t xb = sbase + XP_OFF + (uint32_t)((tn & 1) * 8192);
#pragma unroll
        for (int i = 0; i < 2; i++)
            cp_async16(xb + xp_soff[i], xg + xp_goff[i]);
        CP_COMMIT();
    };

    xp_prefetch(0);

    for (int t = 0; t < TT; t++) {
        const float* __restrict__ cprev = (t == 0) ? cx_in : g_c;
        const __nv_bfloat16* __restrict__ hhi = g_hhi[t & 1];
        const __nv_bfloat16* __restrict__ hlo = g_hlo[t & 1];
        __nv_bfloat16* __restrict__ nhhi = g_hhi[(t + 1) & 1];
        __nv_bfloat16* __restrict__ nhlo = g_hlo[(t + 1) & 1];
        float* __restrict__ out_t = out + (size_t)t * (BB * HH);
        const float* xp_s = (const float*)(smem + XP_OFF + (t & 1) * 8192);

        auto load_chunk = [&](int kc, int st) {
            const uint32_t sb = sbase + A_ST(st);
            const size_t kb = (size_t)kc * 128;
#pragma unroll
            for (int i = 0; i < 2; i++) {
                cp_async16(sb + a_soff[i],        (const char*)hhi + a_goff[i] + kb);
                cp_async16(sb + 8192 + a_soff[i], (const char*)hlo + a_goff[i] + kb);
            }
            CP_COMMIT();
        };

        load_chunk(0, 0);
        load_chunk(1, 1);
        load_chunk(2, 2);
        load_chunk(3, 3);

        float acc_h[2][4][4];
        float acc_m[2][4][4];
#pragma unroll
        for (int mt = 0; mt < 2; mt++)
#pragma unroll
            for (int nt = 0; nt < 4; nt++)
#pragma unroll
                for (int i = 0; i < 4; i++) { acc_h[mt][nt][i] = 0.f; acc_m[mt][nt][i] = 0.f; }

        // 5-stage ring, depth-4 prefetch
        for (int c = 0; c < NCHUNK; c++) {
            if (c <= NCHUNK - 4)      asm volatile("cp.async.wait_group 3;" ::: "memory");
            else if (c == NCHUNK - 3) asm volatile("cp.async.wait_group 2;" ::: "memory");
            else if (c == NCHUNK - 2) asm volatile("cp.async.wait_group 1;" ::: "memory");
            else                      asm volatile("cp.async.wait_group 0;" ::: "memory");
            __syncthreads();

            if (c + 4 < NCHUNK) load_chunk(c + 4, (c + 4) % 5);

            const uint32_t asb = sbase + A_ST(c % 5);
            const uint32_t whb = sbase + W_HI_OFF + (uint32_t)(c * 4096);

            uint32_t ah0[4], ah1[4], al0[4], al1[4], bh0[4], bh1[4], bl0[4], bl1[4];
            ldsm4(ah0, asb + a_off0);
            ldsm4(ah1, asb + a_off1);
            ldsm4(bh0, whb + b_off0);
            ldsm4(bh1, whb + b_off1);
            ldsm4(al0, asb + 8192 + a_off0);
            ldsm4(al1, asb + 8192 + a_off1);
            ldsm4(bl0, whb + 65536 + b_off0);
            ldsm4(bl1, whb + 65536 + b_off1);

            // hi*hi
            mma_bf16(acc_h[0][0], ah0, bh0[0], bh0[1]);
            mma_bf16(acc_h[0][1], ah0, bh0[2], bh0[3]);
            mma_bf16(acc_h[0][2], ah0, bh1[0], bh1[1]);
            mma_bf16(acc_h[0][3], ah0, bh1[2], bh1[3]);
            mma_bf16(acc_h[1][0], ah1, bh0[0], bh0[1]);
            mma_bf16(acc_h[1][1], ah1, bh0[2], bh0[3]);
            mma_bf16(acc_h[1][2], ah1, bh1[0], bh1[1]);
            mma_bf16(acc_h[1][3], ah1, bh1[2], bh1[3]);
            // hi*lo
            mma_bf16(acc_m[0][0], ah0, bl0[0], bl0[1]);
            mma_bf16(acc_m[0][1], ah0, bl0[2], bl0[3]);
            mma_bf16(acc_m[0][2], ah0, bl1[0], bl1[1]);
            mma_bf16(acc_m[0][3], ah0, bl1[2], bl1[3]);
            mma_bf16(acc_m[1][0], ah1, bl0[0], bl0[1]);
            mma_bf16(acc_m[1][1], ah1, bl0[2], bl0[3]);
            mma_bf16(acc_m[1][2], ah1, bl1[0], bl1[1]);
            mma_bf16(acc_m[1][3], ah1, bl1[2], bl1[3]);
            // lo*hi
            mma_bf16(acc_m[0][0], al0, bh0[0], bh0[1]);
            mma_bf16(acc_m[0][1], al0, bh0[2], bh0[3]);
            mma_bf16(acc_m[0][2], al0, bh1[0], bh1[1]);
            mma_bf16(acc_m[0][3], al0, bh1[2], bh1[3]);
            mma_bf16(acc_m[1][0], al1, bh0[0], bh0[1]);
            mma_bf16(acc_m[1][1], al1, bh0[2], bh0[3]);
            mma_bf16(acc_m[1][2], al1, bh1[0], bh1[1]);
            mma_bf16(acc_m[1][3], al1, bh1[2], bh1[3]);
        }

        // ---- k-partial reduction + fused LSTM epilogue ----
        __syncthreads();                   // all ldsm done before ep overlays A
#pragma unroll
        for (int mt = 0; mt < 2; mt++) {
            const int r = mpos * 32 + mt * 16 + grp;
#pragma unroll
            for (int n8 = 0; n8 < 4; n8++) {
                const int ci = n8 * 8 + 2 * tig;
                myep[r * 36 + ci]           = acc_h[mt][n8][0] + acc_m[mt][n8][0];
                myep[r * 36 + ci + 1]       = acc_h[mt][n8][1] + acc_m[mt][n8][1];
                myep[(r + 8) * 36 + ci]     = acc_h[mt][n8][2] + acc_m[mt][n8][2];
                myep[(r + 8) * 36 + ci + 1] = acc_h[mt][n8][3] + acc_m[mt][n8][3];
            }
        }
        __syncthreads();

        // xp(t+1) prefetch (separate buffer; hides under epilogue+barrier)
        if (t + 1 < TT) xp_prefetch(t + 1);

        const int b   = tid >> 2;
        const int jj0 = (tid & 3) * 2;
        const int j0  = cta * 8 + jj0;
        float hq[2], cq[2];
        {
            const float2 cpv = *(const float2*)&cprev[b * HH + j0];
#pragma unroll
            for (int q = 0; q < 2; q++) {
                const int jj = jj0 + q;
                float4 r0 = *(const float4*)&ep[b * 36 + jj * 4];
                float4 r1 = *(const float4*)&ep[2304 + b * 36 + jj * 4];
                float4 r2 = *(const float4*)&ep[4608 + b * 36 + jj * 4];
                float4 r3 = *(const float4*)&ep[6912 + b * 36 + jj * 4];
                float4 xv = *(const float4*)&xp_s[b * 32 + jj * 4];
                float gi = (r0.x + r1.x) + (r2.x + r3.x) + xv.x;
                float gf = (r0.y + r1.y) + (r2.y + r3.y) + xv.y;
                float ga = (r0.z + r1.z) + (r2.z + r3.z) + xv.z;
                float go = (r0.w + r1.w) + (r2.w + r3.w) + xv.w;
                float ig = sigmoidf_(gi);
                float fg = sigmoidf_(gf);
                float ag = tanhf_(ga);
                float og = sigmoidf_(go);
                float cp = (q == 0) ? cpv.x : cpv.y;
                cq[q] = fg * cp + ig * ag;
                hq[q] = og * tanhf_(cq[q]);
            }
            // critical-path stores only: next-step h splits + cell state
            *(float2*)&g_c[b * HH + j0] = make_float2(cq[0], cq[1]);
            float lo0 = hq[0] - __bfloat162float(__float2bfloat16(hq[0]));
            float lo1 = hq[1] - __bfloat162float(__float2bfloat16(hq[1]));
            *(uint32_t*)&nhhi[b * HH + j0] = pk2(hq[0], hq[1]);
            *(uint32_t*)&nhlo[b * HH + j0] = pk2(lo0, lo1);
        }

        if (t + 1 < TT) {
            // barrier arrive gates only on nh/g_c stores
            __syncthreads();
            if (tid == 0) {
                asm volatile("red.release.gpu.global.add.u32 [%0], 1;"
                             :: "l"(&g_bar) : "memory");
            }
            // deferred output store: overlapped with barrier detection
            *(float2*)&out_t[b * HH + j0] = make_float2(hq[0], hq[1]);
            if (tid == 0) {
                const unsigned target = (unsigned)NCTA * (unsigned)(t + 1);
                unsigned v;
                do {
                    asm volatile("ld.global.acquire.gpu.u32 %0, [%1];"
                                 : "=r"(v) : "l"(&g_bar));
                } while (v < target);
            }
            __syncthreads();
        } else {
            // last step: outputs + fused finalize (hy, cy)
            *(float2*)&out_t[b * HH + j0] = make_float2(hq[0], hq[1]);
            const size_t TBH = (size_t)TT * BB * HH;
            *(float2*)&out[TBH + b * HH + j0]                   = make_float2(hq[0], hq[1]);
            *(float2*)&out[TBH + (size_t)BB * HH + b * HH + j0] = make_float2(cq[0], cq[1]);
        }
    }
}

// ---------------------------------------------------------------------------
extern "C" void kernel_launch(void* const* d_in, const int* in_sizes, int n_in,
                              void* d_out, int out_size)
{
    const float* X    = (const float*)d_in[0];
    const float* hx   = (const float*)d_in[1];
    const float* cx   = (const float*)d_in[2];
    const float* w_ii = (const float*)d_in[3];
    const float* w_fi = (const float*)d_in[4];
    const float* w_ai = (const float*)d_in[5];
    const float* w_oi = (const float*)d_in[6];
    const float* w_ih = (const float*)d_in[7];
    const float* w_fh = (const float*)d_in[8];
    const float* w_ah = (const float*)d_in[9];
    const float* w_oh = (const float*)d_in[10];
    const float* b_i  = (const float*)d_in[11];
    const float* b_f  = (const float*)d_in[12];
    const float* b_a  = (const float*)d_in[13];
    const float* b_o  = (const float*)d_in[14];
    float* out = (float*)d_out;

    (void)in_sizes; (void)n_in; (void)out_size;

    cudaFuncSetAttribute(proj_hmma_kernel,
                         cudaFuncAttributeMaxDynamicSharedMemorySize, PSMEM);
    cudaFuncSetAttribute(lstm_persist_kernel,
                         cudaFuncAttributeMaxDynamicSharedMemorySize, SMEM_TOTAL);

    prep_w<<<2 * N4H, 128>>>(w_ih, w_fh, w_ah, w_oh, w_ii, w_fi, w_ai, w_oi);
    prep_x<<<(int)((size_t)MTOT * II / 8 / 256), 256>>>(X);
    prep_h<<<(BB * HH) / 256, 256>>>(hx, b_i, b_f, b_a, b_o);

    dim3 pg(N4H / 128, MTOT / 128);
    proj_hmma_kernel<<<pg, 512, PSMEM>>>();

    lstm_persist_kernel<<<NCTA, 256, SMEM_TOTAL>>>(cx, out);
}